// round 15
// baseline (speedup 1.0000x reference)
#include <cuda_runtime.h>
#include <math.h>

// Problem dims (fixed by the dataset)
#define B_ 256
#define T_ 32
#define V_ 50257
#define D_ 512

typedef unsigned long long ull;

// ---------------------------------------------------------------------------
// Device-global scratch (static allocations are allowed; cudaMalloc is not)
// ---------------------------------------------------------------------------
__device__ float g_sigs[(size_t)V_ * D_];    // normalized signals for the whole vocab
__device__ float g_signq[V_];                // ||sig_v||^2
__device__ float g_state[2][B_ * D_];        // ping-pong state
__device__ float g_snorm2[B_];               // ||state_b||^2
__device__ float g_negit;                    // -1 / softplus(temperature_raw)
__device__ unsigned g_bar[16 * 32];          // per-m-group counters, 128B apart

// ---------------------------------------------------------------------------
// Packed fp32x2 helpers (Blackwell FFMA2/FADD2 — only reachable via PTX)
// ---------------------------------------------------------------------------
__device__ __forceinline__ ull pack2(float x, float y) {
    ull r;
    asm("mov.b64 %0, {%1, %2};" : "=l"(r) : "f"(x), "f"(y));
    return r;
}
__device__ __forceinline__ void unpack2(ull v, float& x, float& y) {
    asm("mov.b64 {%0, %1}, %2;" : "=f"(x), "=f"(y) : "l"(v));
}
__device__ __forceinline__ void ffma2(ull& d, ull a, ull b) {
    asm("fma.rn.f32x2 %0, %1, %2, %0;" : "+l"(d) : "l"(a), "l"(b));
}
__device__ __forceinline__ ull add2(ull a, ull b) {
    ull r;
    asm("add.rn.f32x2 %0, %1, %2;" : "=l"(r) : "l"(a), "l"(b));
    return r;
}

// ---------------------------------------------------------------------------
// Tiny first launch: keeps persist_kernel at the launch index ncu samples.
// ---------------------------------------------------------------------------
__global__ void warm_kernel() {
    if (threadIdx.x == 0) g_negit = 0.0f;
}

// ---------------------------------------------------------------------------
// Signals: embedding row -> LayerNorm (no affine, biased var, eps=1e-5) -> L2
// ---------------------------------------------------------------------------
__global__ __launch_bounds__(128) void sig_kernel(const float* __restrict__ emb) {
    const int r = blockIdx.x;
    const int tid = threadIdx.x;
    const float4 x = ((const float4*)(emb + (size_t)r * D_))[tid];

    float s  = (x.x + x.y) + (x.z + x.w);
    float sq = x.x * x.x + x.y * x.y + x.z * x.z + x.w * x.w;
    #pragma unroll
    for (int o = 16; o > 0; o >>= 1) {
        s  += __shfl_down_sync(0xffffffffu, s, o);
        sq += __shfl_down_sync(0xffffffffu, sq, o);
    }
    __shared__ float ws[4], wq[4];
    const int w = tid >> 5, l = tid & 31;
    if (l == 0) { ws[w] = s; wq[w] = sq; }
    __syncthreads();
    s  = (ws[0] + ws[1]) + (ws[2] + ws[3]);
    sq = (wq[0] + wq[1]) + (wq[2] + wq[3]);

    const float mean = s * (1.0f / D_);
    float var = fmaxf(sq * (1.0f / D_) - mean * mean, 0.0f);
    const float rstd = rsqrtf(var + 1e-5f);
    float nrm = fmaxf(sqrtf((float)D_ * var) * rstd, 1e-12f);
    const float scale = rstd / nrm;

    float4 o;
    o.x = (x.x - mean) * scale;
    o.y = (x.y - mean) * scale;
    o.z = (x.z - mean) * scale;
    o.w = (x.w - mean) * scale;
    ((float4*)(g_sigs + (size_t)r * D_))[tid] = o;
    if (tid == 0) g_signq[r] = (float)D_ * var * scale * scale;   // == ||sig||^2
}

__global__ void zero_kernel() {
    const int i = blockIdx.x * 256 + threadIdx.x;
    g_state[0][i] = 0.0f;
    if (i < 16 * 32) g_bar[i] = 0u;
}

// ---------------------------------------------------------------------------
// Persistent step kernel: all 960 Euler steps in ONE launch.
// Grid (16 n-slices x 8 group-pairs) = 128 CTAs, 512 threads, 1 CTA/SM.
//
// LATENCY-HIDING INTERLEAVE: each CTA serves TWO independent m-groups (g and
// g+8) on the same 32-column n-slice. Per step: waitA, workA, arriveA, waitB,
// workB, arriveB — group B's full compute sits between A's arrive and A's
// next wait, absorbing barrier latency and inter-CTA skew (waits hit the
// fast path). sA/part/pmean buffers are time-shared (syncs order the reuse).
//
// Per-group tile: 16m x 32n x 512k; 16-way k-split (1 warp per 32-k slice),
// per-thread 2m x 8n via FFMA2 pairs along n. Partials stored lane-major
// (4x STS.128 per thread, conflict-free) — fixes R14's 8-way STS conflict.
// ---------------------------------------------------------------------------
#define SB_OFF    0                              // float [512][36]   73728 B
#define SA_OFF    73728                          // float [16][516]   33024 B
#define PART_OFF  (SA_OFF + 16 * 516 * 4)        // ull  [16*256]     32768 B
#define PMEAN_OFF (PART_OFF + 16 * 256 * 8)      // float [16][36]     2304 B
#define SMEAN_OFF (PMEAN_OFF + 16 * 36 * 4)      // float [16]
#define STEP_SMEM (SMEAN_OFF + 64)               // 141888 B

__global__ __launch_bounds__(512, 1) void persist_kernel(const float* __restrict__ dif,
                                                         const int* __restrict__ ids) {
    extern __shared__ unsigned char sm[];
    float* sB    = (float*)(sm + SB_OFF);     // [k][36] (32 n + pad)
    float* sA    = (float*)(sm + SA_OFF);     // [16 m][516] full rows (time-shared)
    ull*   part  = (ull*)(sm + PART_OFF);     // [16 g][lane*8+slot] (time-shared)
    float* pmean = (float*)(sm + PMEAN_OFF);  // [16 m][36]
    float* smean = (float*)(sm + SMEAN_OFF);  // [16]

    const int tid = threadIdx.x;
    const int n0  = blockIdx.x * 32;
    const int gp  = blockIdx.y;               // group pair: groups gp, gp+8
    const int mrow0_[2] = { gp * 16, (gp + 8) * 16 };
    volatile unsigned* barp_[2] = { &g_bar[gp * 32], &g_bar[(gp + 8) * 32] };

    // ---- one-time: diffusion slice k-major into sB ----
    {
        const int n = tid >> 4, q = tid & 15;
        const float* drow = dif + (size_t)(n0 + n) * D_;
        #pragma unroll
        for (int i = 0; i < 8; i++) {
            const int k4 = q * 8 + i;
            const float4 v = *(const float4*)(drow + k4 * 4);
            sB[(k4 * 4 + 0) * 36 + n] = v.x;
            sB[(k4 * 4 + 1) * 36 + n] = v.y;
            sB[(k4 * 4 + 2) * 36 + n] = v.z;
            sB[(k4 * 4 + 3) * 36 + n] = v.w;
        }
    }
    __syncthreads();

    // GEMM mapping: 16 k-groups (32 k each, one warp) x (4 tx n-quarters x 8 tmy m-pairs)
    const int wg   = tid >> 5;
    const int lane = tid & 31;
    const int tx   = lane & 3;
    const int tmy  = lane >> 2;
    const int kbeg = wg * 32;

    // phase-1 mapping: 16 rows x 32 float4-lanes
    const int pm = tid >> 5, pl = tid & 31;

    // phase-3 mapping (tid < 256): em = row, enp = n-pair index (n = 2*enp)
    const int em  = tid >> 4;
    const int enp = tid & 15;
    const int dgl = n0 + 2 * enp;
    int p3off;
    {
        const int r = em & 1;
        int t3, s3;
        if (enp < 8) { t3 = enp >> 1;        s3 = r * 4 + (enp & 1); }
        else         { t3 = (enp - 8) >> 1;  s3 = r * 4 + 2 + (enp & 1); }
        p3off = ((em >> 1) * 4 + t3) * 8 + s3;     // lane*8 + slot
    }

    // per-token register caches (one per group)
    int    tcur_[2] = { -1, -1 };
    float2 sgr_[2]  = { make_float2(0.f, 0.f), make_float2(0.f, 0.f) };

    for (int step = 0; step < 960; step++) {
        const float* __restrict__ src = g_state[step & 1];
        float* __restrict__ dst = g_state[(step + 1) & 1];
        const int t = step / 30;
        const unsigned target = 16u * (unsigned)step;

        #pragma unroll
        for (int h = 0; h < 2; h++) {
            const int m0 = mrow0_[h];
            volatile unsigned* bar = barp_[h];

            // ---- wait: peers finished writing state[step] for this group ----
            if (tid == 0) { while (*bar < target) { } }
            __syncthreads();

            // ---- token-boundary signal refresh (overlaps later phases) ----
            if (t != tcur_[h]) {
                tcur_[h] = t;
                if (tid < 256) {
                    const int id = __ldg(&ids[(m0 + em) * T_ + t]);
                    sgr_[h] = *(const float2*)(g_sigs + (size_t)id * D_ + dgl);
                }
            }

            // ---- phase 1: coalesced copy of 16 state rows + mean partials ----
            {
                const float4* srow = (const float4*)(src + (size_t)(m0 + pm) * D_);
                float4* arow = (float4*)(sA + pm * 516);
                float s = 0.f;
                #pragma unroll
                for (int j = 0; j < 4; j++) {
                    const float4 v = __ldcg(srow + pl + 32 * j);
                    arow[pl + 32 * j] = v;
                    s += (v.x + v.y) + (v.z + v.w);
                }
                pmean[pm * 36 + pl] = s;
            }
            __syncthreads();

            if (tid < 16) {
                const float4* pr = (const float4*)(pmean + tid * 36);
                float4 a = pr[0];
                #pragma unroll
                for (int j = 1; j < 8; j++) {
                    const float4 b = pr[j];
                    a.x += b.x; a.y += b.y; a.z += b.z; a.w += b.w;
                }
                smean[tid] = ((a.x + a.y) + (a.z + a.w)) * (1.0f / D_);
            }

            // ---- phase 2: GEMM partial over this warp's 32 k ----
            {
                const float* Ar0 = sA + (2 * tmy) * 516;
                const float* Ar1 = Ar0 + 516;
                const float* Bp  = sB + tx * 4;
                ull a0 = 0, a1 = 0, a2 = 0, a3 = 0, a4 = 0, a5 = 0, a6 = 0, a7 = 0;
                const int kend = kbeg + 32;
                #pragma unroll 4
                for (int kk = kbeg; kk < kend; kk += 4) {
                    const float4 av0 = *(const float4*)(Ar0 + kk);
                    const float4 av1 = *(const float4*)(Ar1 + kk);
                    #pragma unroll
                    for (int u = 0; u < 4; u++) {
                        const float s0 = (&av0.x)[u], s1 = (&av1.x)[u];
                        const ull A0 = pack2(s0, s0);
                        const ull A1 = pack2(s1, s1);
                        const float* br = Bp + (kk + u) * 36;
                        const ulonglong2 bl = *(const ulonglong2*)(br);
                        const ulonglong2 bh = *(const ulonglong2*)(br + 16);
                        ffma2(a0, A0, bl.x); ffma2(a1, A0, bl.y);
                        ffma2(a2, A0, bh.x); ffma2(a3, A0, bh.y);
                        ffma2(a4, A1, bl.x); ffma2(a5, A1, bl.y);
                        ffma2(a6, A1, bh.x); ffma2(a7, A1, bh.y);
                    }
                }
                // lane-major partial store: 4 x STS.128, conflict-free-ish
                ull* base = part + wg * 256 + lane * 8;
                ulonglong2 w0, w1, w2, w3;
                w0.x = a0; w0.y = a1; w1.x = a2; w1.y = a3;
                w2.x = a4; w2.y = a5; w3.x = a6; w3.y = a7;
                *(ulonglong2*)(base + 0) = w0;
                *(ulonglong2*)(base + 2) = w1;
                *(ulonglong2*)(base + 4) = w2;
                *(ulonglong2*)(base + 6) = w3;
            }
            __syncthreads();

            // ---- phase 3: 16-way k reduction + fused epilogue ----
            if (tid < 256) {
                const ull* pb = part + p3off;
                ull sA0 = add2(add2(add2(pb[0],    pb[256]),  add2(pb[512],  pb[768])),
                               add2(add2(pb[1024], pb[1280]), add2(pb[1536], pb[1792])));
                ull sA1 = add2(add2(add2(pb[2048], pb[2304]), add2(pb[2560], pb[2816])),
                               add2(add2(pb[3072], pb[3328]), add2(pb[3584], pb[3840])));
                ull s = add2(sA0, sA1);
                float d0, d1;
                unpack2(s, d0, d1);

                const float2 iv = *(const float2*)(sA + em * 516 + dgl);
                const float mean = smean[em];
                const int b = m0 + em;

                const float in_[2] = { iv.x, iv.y };
                const float dd_[2] = { d0, d1 };
                const float sg_[2] = { sgr_[h].x, sgr_[h].y };
                float o_[2];
                #pragma unroll
                for (int j = 0; j < 2; j++) {
                    const float c = in_[j] - mean;
                    const float drift = dd_[j] + 0.008f * c * c * c + sg_[j];
                    float v = in_[j] + 0.04f * drift;
                    if (!isfinite(v)) v = 0.0f;
                    o_[j] = fminf(fmaxf(v, -80.0f), 80.0f);
                }
                *(float2*)(dst + (size_t)b * D_ + dgl) = make_float2(o_[0], o_[1]);
            }
            __syncthreads();

            // ---- arrive: publish this group's dst slice ----
            if (tid == 0) {
                __threadfence();
                atomicAdd((unsigned*)bar, 1u);
            }
        }
    }
}

// ---------------------------------------------------------------------------
// ||state_b||^2 and -1/softplus(temp). One warp per batch row.
// ---------------------------------------------------------------------------
__global__ void snorm_kernel(const float* __restrict__ traw) {
    const int b = blockIdx.x, lane = threadIdx.x;
    const float4* p4 = (const float4*)(g_state[0] + b * D_);
    float s = 0.f;
    #pragma unroll
    for (int j = 0; j < 4; j++) {
        const float4 v = p4[j * 32 + lane];
        s += v.x * v.x + v.y * v.y + v.z * v.z + v.w * v.w;
    }
    #pragma unroll
    for (int o = 16; o > 0; o >>= 1) s += __shfl_down_sync(0xffffffffu, s, o);
    if (lane == 0) g_snorm2[b] = s;
    if (b == 0 && lane == 0) {
        const float x = traw[0];
        float sp = log1pf(expf(x));
        sp = fmaxf(sp, 1e-6f);
        g_negit = -1.0f / sp;
    }
}

// ---------------------------------------------------------------------------
// Logits: out[b,v] = -sqrt(max(||s_b||^2 + ||g_v||^2 - 2 s_b.g_v, 0)) / temp
// Tile: 32m x 64v per CTA, micro 2m x 8v via packed FFMA2.
// ---------------------------------------------------------------------------
__global__ __launch_bounds__(128) void logits_kernel(float* __restrict__ out) {
    __shared__ float sA[32][36];   // state tile [m][k]
    __shared__ float sB[32][68];   // signals tile, k-major [k][v]

    const float* __restrict__ st = g_state[0];
    const int tid = threadIdx.x;
    const int v0 = blockIdx.x * 64;
    const int m0 = blockIdx.y * 32;
    const int tx = tid & 7, ty = tid >> 3;

    ull acc[2][4] = {};

    for (int k0 = 0; k0 < D_; k0 += 32) {
        __syncthreads();
        #pragma unroll
        for (int i = 0; i < 2; i++) {
            const int idx = tid + i * 128;
            const int r = idx >> 3, c = idx & 7;
            *(float4*)&sA[r][c * 4] =
                *(const float4*)(st + (size_t)(m0 + r) * D_ + k0 + c * 4);
        }
        #pragma unroll
        for (int i = 0; i < 4; i++) {
            const int idx = tid + i * 128;
            const int r = idx >> 3, c = idx & 7;
            const int v = v0 + r;
            float4 x = make_float4(0.f, 0.f, 0.f, 0.f);
            if (v < V_) x = *(const float4*)(g_sigs + (size_t)v * D_ + k0 + c * 4);
            sB[c * 4 + 0][r] = x.x;
            sB[c * 4 + 1][r] = x.y;
            sB[c * 4 + 2][r] = x.z;
            sB[c * 4 + 3][r] = x.w;
        }
        __syncthreads();
        #pragma unroll
        for (int kk = 0; kk < 32; kk++) {
            const float a0 = sA[ty * 2 + 0][kk];
            const float a1 = sA[ty * 2 + 1][kk];
            const ull aa0 = pack2(a0, a0);
            const ull aa1 = pack2(a1, a1);
            const ulonglong2 b01 = *(const ulonglong2*)&sB[kk][tx * 8];
            const ulonglong2 b23 = *(const ulonglong2*)&sB[kk][tx * 8 + 4];
            ffma2(acc[0][0], aa0, b01.x); ffma2(acc[0][1], aa0, b01.y);
            ffma2(acc[0][2], aa0, b23.x); ffma2(acc[0][3], aa0, b23.y);
            ffma2(acc[1][0], aa1, b01.x); ffma2(acc[1][1], aa1, b01.y);
            ffma2(acc[1][2], aa1, b23.x); ffma2(acc[1][3], aa1, b23.y);
        }
    }

    const float negit = g_negit;
    #pragma unroll
    for (int mi = 0; mi < 2; mi++) {
        const int b = m0 + ty * 2 + mi;
        const float sn = g_snorm2[b];
        #pragma unroll
        for (int pj = 0; pj < 4; pj++) {
            float d0, d1;
            unpack2(acc[mi][pj], d0, d1);
            const int v = v0 + tx * 8 + pj * 2;
            if (v < V_) {
                const float sq = fmaxf(sn + g_signq[v] - 2.0f * d0, 0.0f);
                out[(size_t)b * V_ + v] = sqrtf(sq) * negit;
            }
            if (v + 1 < V_) {
                const float sq = fmaxf(sn + g_signq[v + 1] - 2.0f * d1, 0.0f);
                out[(size_t)b * V_ + v + 1] = sqrtf(sq) * negit;
            }
        }
    }
}

// ---------------------------------------------------------------------------
// Launch: 6 graph nodes (warm first so persist sits at the sampled position).
// ---------------------------------------------------------------------------
extern "C" void kernel_launch(void* const* d_in, const int* in_sizes, int n_in,
                              void* d_out, int out_size) {
    const int*   ids  = nullptr;
    const float* emb  = nullptr;
    const float* dif  = nullptr;
    const float* traw = nullptr;
    for (int i = 0; i < n_in; i++) {
        switch (in_sizes[i]) {
            case B_ * T_:  ids  = (const int*)d_in[i];   break;
            case V_ * D_:  emb  = (const float*)d_in[i]; break;
            case D_ * D_:  dif  = (const float*)d_in[i]; break;
            case 1:        traw = (const float*)d_in[i]; break;
        }
    }
    float* out = (float*)d_out;

    static bool attr_set = false;
    if (!attr_set) {
        cudaFuncSetAttribute(persist_kernel,
                             cudaFuncAttributeMaxDynamicSharedMemorySize, STEP_SMEM);
        attr_set = true;
    }

    warm_kernel<<<1, 32>>>();
    sig_kernel<<<V_, 128>>>(emb);
    zero_kernel<<<(B_ * D_) / 256, 256>>>();
    persist_kernel<<<dim3(16, 8), 512, STEP_SMEM>>>(dif, ids);
    snorm_kernel<<<B_, 32>>>(traw);
    logits_kernel<<<dim3((V_ + 63) / 64, B_ / 32), 128>>>(out);
    (void)out_size;
}

// round 17
// speedup vs baseline: 1.2174x; 1.2174x over previous
#include <cuda_runtime.h>
#include <math.h>

// Problem dims (fixed by the dataset)
#define B_ 256
#define T_ 32
#define V_ 50257
#define D_ 512

typedef unsigned long long ull;

// ---------------------------------------------------------------------------
// Device-global scratch (static allocations are allowed; cudaMalloc is not)
// ---------------------------------------------------------------------------
__device__ float g_sigs[(size_t)V_ * D_];    // normalized signals for the whole vocab
__device__ float g_signq[V_];                // ||sig_v||^2
__device__ float g_state[2][B_ * D_];        // ping-pong state
__device__ float g_snorm2[B_];               // ||state_b||^2
__device__ float g_negit;                    // -1 / softplus(temperature_raw)
__device__ unsigned g_bar[16 * 32];          // per-m-group counters, 128B apart

// ---------------------------------------------------------------------------
// Packed fp32x2 helpers (Blackwell FFMA2/FADD2 — only reachable via PTX)
// ---------------------------------------------------------------------------
__device__ __forceinline__ ull pack2(float x, float y) {
    ull r;
    asm("mov.b64 %0, {%1, %2};" : "=l"(r) : "f"(x), "f"(y));
    return r;
}
__device__ __forceinline__ void unpack2(ull v, float& x, float& y) {
    asm("mov.b64 {%0, %1}, %2;" : "=f"(x), "=f"(y) : "l"(v));
}
__device__ __forceinline__ void ffma2(ull& d, ull a, ull b) {
    asm("fma.rn.f32x2 %0, %1, %2, %0;" : "+l"(d) : "l"(a), "l"(b));
}
__device__ __forceinline__ ull add2(ull a, ull b) {
    ull r;
    asm("add.rn.f32x2 %0, %1, %2;" : "=l"(r) : "l"(a), "l"(b));
    return r;
}

// ---------------------------------------------------------------------------
// Tiny first launch: keeps persist_kernel at the launch index ncu samples.
// ---------------------------------------------------------------------------
__global__ void warm_kernel() {
    if (threadIdx.x == 0) g_negit = 0.0f;
}

// ---------------------------------------------------------------------------
// Signals: embedding row -> LayerNorm (no affine, biased var, eps=1e-5) -> L2
// ---------------------------------------------------------------------------
__global__ __launch_bounds__(128) void sig_kernel(const float* __restrict__ emb) {
    const int r = blockIdx.x;
    const int tid = threadIdx.x;
    const float4 x = ((const float4*)(emb + (size_t)r * D_))[tid];

    float s  = (x.x + x.y) + (x.z + x.w);
    float sq = x.x * x.x + x.y * x.y + x.z * x.z + x.w * x.w;
    #pragma unroll
    for (int o = 16; o > 0; o >>= 1) {
        s  += __shfl_down_sync(0xffffffffu, s, o);
        sq += __shfl_down_sync(0xffffffffu, sq, o);
    }
    __shared__ float ws[4], wq[4];
    const int w = tid >> 5, l = tid & 31;
    if (l == 0) { ws[w] = s; wq[w] = sq; }
    __syncthreads();
    s  = (ws[0] + ws[1]) + (ws[2] + ws[3]);
    sq = (wq[0] + wq[1]) + (wq[2] + wq[3]);

    const float mean = s * (1.0f / D_);
    float var = fmaxf(sq * (1.0f / D_) - mean * mean, 0.0f);
    const float rstd = rsqrtf(var + 1e-5f);
    float nrm = fmaxf(sqrtf((float)D_ * var) * rstd, 1e-12f);
    const float scale = rstd / nrm;

    float4 o;
    o.x = (x.x - mean) * scale;
    o.y = (x.y - mean) * scale;
    o.z = (x.z - mean) * scale;
    o.w = (x.w - mean) * scale;
    ((float4*)(g_sigs + (size_t)r * D_))[tid] = o;
    if (tid == 0) g_signq[r] = (float)D_ * var * scale * scale;   // == ||sig||^2
}

__global__ void zero_kernel() {
    const int i = blockIdx.x * 256 + threadIdx.x;
    g_state[0][i] = 0.0f;
    if (i < 16 * 32) g_bar[i] = 0u;
}

// ---------------------------------------------------------------------------
// Persistent step kernel: all 960 Euler steps in ONE launch.
// Grid (8 n-tiles x 16 m-groups) = 128 CTAs, 512 threads, 1 CTA/SM.
//
// R14 dataflow with phase-1 A staging removed: each 2-warp k-group streams
// its private 16m x 64k A-slice straight from gmem (L2) into a software-
// pipelined register buffer inside the GEMM loop. Row means: warp w owns
// row w. Phase-3 mapping is R14's (em=tid>>5, enp=tid&31, ALL 512 threads,
// 1024 floats/tile — R16's bug wrote only half the tile). 2 syncs/step.
// ---------------------------------------------------------------------------
#define SB_OFF    0                              // float [512][68]  139264 B
#define PART_OFF  139264                         // ull  [8][512]     32768 B
#define SMEAN_OFF (PART_OFF + 8 * 512 * 8)       // float [16]
#define STEP_SMEM (SMEAN_OFF + 64)               // 172096 B

__global__ __launch_bounds__(512, 1) void persist_kernel(const float* __restrict__ dif,
                                                         const int* __restrict__ ids) {
    extern __shared__ unsigned char sm[];
    float* sB    = (float*)(sm + SB_OFF);     // [k][68] (64 n + pad)
    ull*   part  = (ull*)(sm + PART_OFF);     // [8 g][512 pairs]
    float* smean = (float*)(sm + SMEAN_OFF);  // [16]

    const int tid = threadIdx.x;
    const int n0  = blockIdx.x * 64;
    const int mg  = blockIdx.y;
    const int m0  = mg * 16;
    volatile unsigned* bar = &g_bar[mg * 32];

    // ---- one-time: diffusion slice k-major into sB ----
    {
        const int n = tid >> 3, q = tid & 7;
        const float* drow = dif + (size_t)(n0 + n) * D_;
        #pragma unroll
        for (int i = 0; i < 16; i++) {
            const int k4 = q * 16 + i;
            const float4 v = *(const float4*)(drow + k4 * 4);
            sB[(k4 * 4 + 0) * 68 + n] = v.x;
            sB[(k4 * 4 + 1) * 68 + n] = v.y;
            sB[(k4 * 4 + 2) * 68 + n] = v.z;
            sB[(k4 * 4 + 3) * 68 + n] = v.w;
        }
    }
    __syncthreads();

    // GEMM mapping: 8 k-groups (64 k, 2 warps) x (8 tx n-octs x 8 tmy m-pairs)
    const int g   = tid >> 6;
    const int lcl = tid & 63;
    const int tx  = lcl & 7;
    const int tmy = lcl >> 3;
    const int kbeg = g * 64;

    // mean mapping: warp w owns row w
    const int w = tid >> 5, lane = tid & 31;

    // phase-3 mapping (R14): em = row (tid>>5), enp = n-pair (tid&31), all 512
    const int em  = tid >> 5;
    const int enp = tid & 31;
    const int dgl = n0 + 2 * enp;

    // per-token register cache (refreshed every 30 steps)
    int    tcur = -1;
    float2 sgreg = make_float2(0.f, 0.f);

    for (int step = 0; step < 960; step++) {
        const float* __restrict__ src = g_state[step & 1];
        float* __restrict__ dst = g_state[(step + 1) & 1];

        // ---- prefetch epilogue inputs (src ready: end-of-prev-step barrier) ----
        const float2 iv = __ldcg((const float2*)(src + (size_t)(m0 + em) * D_ + dgl));

        // ---- token-boundary signal refresh (overlaps GEMM) ----
        const int t = step / 30;
        if (t != tcur) {
            tcur = t;
            const int id = __ldg(&ids[(m0 + em) * T_ + t]);
            sgreg = *(const float2*)(g_sigs + (size_t)id * D_ + dgl);
        }

        // ---- row means: warp w reduces row w (consumed in phase 3) ----
        {
            const float4* srow = (const float4*)(src + (size_t)(m0 + w) * D_);
            float s = 0.f;
            #pragma unroll
            for (int j = 0; j < 4; j++) {
                const float4 v = __ldcg(srow + lane + 32 * j);
                s += (v.x + v.y) + (v.z + v.w);
            }
            #pragma unroll
            for (int o = 16; o > 0; o >>= 1) s += __shfl_down_sync(0xffffffffu, s, o);
            if (lane == 0) smean[w] = s * (1.0f / D_);
        }

        // ---- phase 2: GEMM partial, A streamed from gmem (pipelined chunks) ----
        {
            const float4* Ar0 = (const float4*)(src + (size_t)(m0 + 2 * tmy) * D_ + kbeg);
            const float4* Ar1 = (const float4*)(src + (size_t)(m0 + 2 * tmy + 1) * D_ + kbeg);
            const float* Bp = sB + tx * 4;

            float4 p0a = __ldcg(Ar0 + 0), p0b = __ldcg(Ar0 + 1);
            float4 p1a = __ldcg(Ar1 + 0), p1b = __ldcg(Ar1 + 1);

            ull a0 = 0, a1 = 0, a2 = 0, a3 = 0, a4 = 0, a5 = 0, a6 = 0, a7 = 0;

            #pragma unroll
            for (int c = 0; c < 8; c++) {         // 8 chunks x 8 k = 64 k
                float4 q0a, q0b, q1a, q1b;
                if (c < 7) {
                    q0a = __ldcg(Ar0 + 2 * c + 2); q0b = __ldcg(Ar0 + 2 * c + 3);
                    q1a = __ldcg(Ar1 + 2 * c + 2); q1b = __ldcg(Ar1 + 2 * c + 3);
                }
                const int k8 = kbeg + c * 8;
                #pragma unroll
                for (int u = 0; u < 4; u++) {
                    const float s0 = (&p0a.x)[u], s1 = (&p1a.x)[u];
                    const ull A0 = pack2(s0, s0);
                    const ull A1 = pack2(s1, s1);
                    const float* br = Bp + (k8 + u) * 68;
                    const ulonglong2 bl = *(const ulonglong2*)(br);
                    const ulonglong2 bh = *(const ulonglong2*)(br + 32);
                    ffma2(a0, A0, bl.x); ffma2(a1, A0, bl.y);
                    ffma2(a2, A0, bh.x); ffma2(a3, A0, bh.y);
                    ffma2(a4, A1, bl.x); ffma2(a5, A1, bl.y);
                    ffma2(a6, A1, bh.x); ffma2(a7, A1, bh.y);
                }
                #pragma unroll
                for (int u = 0; u < 4; u++) {
                    const float s0 = (&p0b.x)[u], s1 = (&p1b.x)[u];
                    const ull A0 = pack2(s0, s0);
                    const ull A1 = pack2(s1, s1);
                    const float* br = Bp + (k8 + 4 + u) * 68;
                    const ulonglong2 bl = *(const ulonglong2*)(br);
                    const ulonglong2 bh = *(const ulonglong2*)(br + 32);
                    ffma2(a0, A0, bl.x); ffma2(a1, A0, bl.y);
                    ffma2(a2, A0, bh.x); ffma2(a3, A0, bh.y);
                    ffma2(a4, A1, bl.x); ffma2(a5, A1, bl.y);
                    ffma2(a6, A1, bh.x); ffma2(a7, A1, bh.y);
                }
                p0a = q0a; p0b = q0b; p1a = q1a; p1b = q1b;
            }

            // pair flat id = m*32 + np;  np = tx*2 (+1) and tx*2+16 (+17)
            ull* p0 = part + g * 512 + (2 * tmy) * 32 + tx * 2;
            p0[0]  = a0; p0[1]  = a1; p0[16] = a2; p0[17] = a3;
            ull* p1 = p0 + 32;
            p1[0]  = a4; p1[1]  = a5; p1[16] = a6; p1[17] = a7;
        }
        __syncthreads();

        // ---- phase 3: k-split reduction + fused epilogue (all 512 threads) ----
        {
            const ull* pb = part + em * 32 + enp;
            ull s = add2(add2(pb[0], pb[512]), add2(pb[1024], pb[1536]));
            s = add2(s, add2(add2(pb[2048], pb[2560]), add2(pb[3072], pb[3584])));
            float d0, d1;
            unpack2(s, d0, d1);

            const float mean = smean[em];
            const int b = m0 + em;

            const float in_[2] = { iv.x, iv.y };
            const float dd_[2] = { d0, d1 };
            const float sg_[2] = { sgreg.x, sgreg.y };
            float o_[2];
            #pragma unroll
            for (int j = 0; j < 2; j++) {
                const float c = in_[j] - mean;
                const float drift = dd_[j] + 0.008f * c * c * c + sg_[j];
                float v = in_[j] + 0.04f * drift;
                if (!isfinite(v)) v = 0.0f;
                o_[j] = fminf(fmaxf(v, -80.0f), 80.0f);
            }
            *(float2*)(dst + (size_t)b * D_ + dgl) = make_float2(o_[0], o_[1]);
        }

        // ---- phase 4: m-group barrier (8 CTAs), private 128B line ----
        __syncthreads();
        if (tid == 0) {
            __threadfence();
            atomicAdd((unsigned*)bar, 1u);
            const unsigned target = 8u * (unsigned)(step + 1);
            while (*bar < target) { }
            __threadfence();
        }
        __syncthreads();
    }
}

// ---------------------------------------------------------------------------
// ||state_b||^2 and -1/softplus(temp). One warp per batch row.
// ---------------------------------------------------------------------------
__global__ void snorm_kernel(const float* __restrict__ traw) {
    const int b = blockIdx.x, lane = threadIdx.x;
    const float4* p4 = (const float4*)(g_state[0] + b * D_);
    float s = 0.f;
    #pragma unroll
    for (int j = 0; j < 4; j++) {
        const float4 v = p4[j * 32 + lane];
        s += v.x * v.x + v.y * v.y + v.z * v.z + v.w * v.w;
    }
    #pragma unroll
    for (int o = 16; o > 0; o >>= 1) s += __shfl_down_sync(0xffffffffu, s, o);
    if (lane == 0) g_snorm2[b] = s;
    if (b == 0 && lane == 0) {
        const float x = traw[0];
        float sp = log1pf(expf(x));
        sp = fmaxf(sp, 1e-6f);
        g_negit = -1.0f / sp;
    }
}

// ---------------------------------------------------------------------------
// Logits: out[b,v] = -sqrt(max(||s_b||^2 + ||g_v||^2 - 2 s_b.g_v, 0)) / temp
// Tile: 32m x 64v per CTA, micro 2m x 8v via packed FFMA2.
// ---------------------------------------------------------------------------
__global__ __launch_bounds__(128) void logits_kernel(float* __restrict__ out) {
    __shared__ float sA[32][36];   // state tile [m][k]
    __shared__ float sB[32][68];   // signals tile, k-major [k][v]

    const float* __restrict__ st = g_state[0];
    const int tid = threadIdx.x;
    const int v0 = blockIdx.x * 64;
    const int m0 = blockIdx.y * 32;
    const int tx = tid & 7, ty = tid >> 3;

    ull acc[2][4] = {};

    for (int k0 = 0; k0 < D_; k0 += 32) {
        __syncthreads();
        #pragma unroll
        for (int i = 0; i < 2; i++) {
            const int idx = tid + i * 128;
            const int r = idx >> 3, c = idx & 7;
            *(float4*)&sA[r][c * 4] =
                *(const float4*)(st + (size_t)(m0 + r) * D_ + k0 + c * 4);
        }
        #pragma unroll
        for (int i = 0; i < 4; i++) {
            const int idx = tid + i * 128;
            const int r = idx >> 3, c = idx & 7;
            const int v = v0 + r;
            float4 x = make_float4(0.f, 0.f, 0.f, 0.f);
            if (v < V_) x = *(const float4*)(g_sigs + (size_t)v * D_ + k0 + c * 4);
            sB[c * 4 + 0][r] = x.x;
            sB[c * 4 + 1][r] = x.y;
            sB[c * 4 + 2][r] = x.z;
            sB[c * 4 + 3][r] = x.w;
        }
        __syncthreads();
        #pragma unroll
        for (int kk = 0; kk < 32; kk++) {
            const float a0 = sA[ty * 2 + 0][kk];
            const float a1 = sA[ty * 2 + 1][kk];
            const ull aa0 = pack2(a0, a0);
            const ull aa1 = pack2(a1, a1);
            const ulonglong2 b01 = *(const ulonglong2*)&sB[kk][tx * 8];
            const ulonglong2 b23 = *(const ulonglong2*)&sB[kk][tx * 8 + 4];
            ffma2(acc[0][0], aa0, b01.x); ffma2(acc[0][1], aa0, b01.y);
            ffma2(acc[0][2], aa0, b23.x); ffma2(acc[0][3], aa0, b23.y);
            ffma2(acc[1][0], aa1, b01.x); ffma2(acc[1][1], aa1, b01.y);
            ffma2(acc[1][2], aa1, b23.x); ffma2(acc[1][3], aa1, b23.y);
        }
    }

    const float negit = g_negit;
    #pragma unroll
    for (int mi = 0; mi < 2; mi++) {
        const int b = m0 + ty * 2 + mi;
        const float sn = g_snorm2[b];
        #pragma unroll
        for (int pj = 0; pj < 4; pj++) {
            float d0, d1;
            unpack2(acc[mi][pj], d0, d1);
            const int v = v0 + tx * 8 + pj * 2;
            if (v < V_) {
                const float sq = fmaxf(sn + g_signq[v] - 2.0f * d0, 0.0f);
                out[(size_t)b * V_ + v] = sqrtf(sq) * negit;
            }
            if (v + 1 < V_) {
                const float sq = fmaxf(sn + g_signq[v + 1] - 2.0f * d1, 0.0f);
                out[(size_t)b * V_ + v + 1] = sqrtf(sq) * negit;
            }
        }
    }
}

// ---------------------------------------------------------------------------
// Launch: 6 graph nodes (warm first so persist sits at the sampled position).
// ---------------------------------------------------------------------------
extern "C" void kernel_launch(void* const* d_in, const int* in_sizes, int n_in,
                              void* d_out, int out_size) {
    const int*   ids  = nullptr;
    const float* emb  = nullptr;
    const float* dif  = nullptr;
    const float* traw = nullptr;
    for (int i = 0; i < n_in; i++) {
        switch (in_sizes[i]) {
            case B_ * T_:  ids  = (const int*)d_in[i];   break;
            case V_ * D_:  emb  = (const float*)d_in[i]; break;
            case D_ * D_:  dif  = (const float*)d_in[i]; break;
            case 1:        traw = (const float*)d_in[i]; break;
        }
    }
    float* out = (float*)d_out;

    static bool attr_set = false;
    if (!attr_set) {
        cudaFuncSetAttribute(persist_kernel,
                             cudaFuncAttributeMaxDynamicSharedMemorySize, STEP_SMEM);
        attr_set = true;
    }

    warm_kernel<<<1, 32>>>();
    sig_kernel<<<V_, 128>>>(emb);
    zero_kernel<<<(B_ * D_) / 256, 256>>>();
    persist_kernel<<<dim3(8, 16), 512, STEP_SMEM>>>(dif, ids);
    snorm_kernel<<<B_, 32>>>(traw);
    logits_kernel<<<dim3((V_ + 63) / 64, B_ / 32), 128>>>(out);
    (void)out_size;
}